// round 13
// baseline (speedup 1.0000x reference)
#include <cuda_runtime.h>
#include <cstdint>

#define KDIM   8192
#define N4     6144
#define N8     2048
#define NTOT   8192
#define MROWS  16
#define KSEGS  16
#define KSPAN  (KDIM / KSEGS)     // 512
#define CHUNKK 16                 // k per weight pipeline chunk
#define NCHUNK (KSPAN / CHUNKK)   // 32
#define COLSPB 512                // columns per block (2 per thread)
#define TPB    256

// dynamic smem: 2 weight stages x (4 iw x 512 cols) int4 = 64 KB
#define WS_INT4S   2048
#define SMEM_BYTES (2 * WS_INT4S * 16)

typedef unsigned long long ull;

// Scratch (device globals; no runtime allocation)
__device__ __align__(16) float g_x2t[KDIM * MROWS];           // 512 KB transposed x2 [k][m]
__device__ __align__(16) float g_part[KSEGS][MROWS][NTOT];    // 8 MB partial slabs
__device__ __align__(16) float g_sum[MROWS][NTOT];            // 512 KB

// int (0 <= w < 2^22) -> float(2^23 + w), exact, one LOP3
__device__ __forceinline__ float biasf(int w) {
    return __uint_as_float(0x4B000000u | (unsigned)w);
}
// cp.async 16B, global -> shared, L2-only (.cg)
__device__ __forceinline__ void cpasync16(void* smem, const void* gmem) {
    uint32_t s = (uint32_t)__cvta_generic_to_shared(smem);
    asm volatile("cp.async.cg.shared.global [%0], [%1], 16;" :: "r"(s), "l"(gmem) : "memory");
}
__device__ __forceinline__ void cp_commit() {
    asm volatile("cp.async.commit_group;" ::: "memory");
}
template <int N>
__device__ __forceinline__ void cp_wait() {
    asm volatile("cp.async.wait_group %0;" :: "n"(N) : "memory");
}

// -------- Kernel 1: transpose+scale: g_x2t[k*16+m] = x[m][k] / awq[k] --------
// 32768 threads: k fast (coalesced), m-quad slow; each thread owns one 16B cell.
__global__ void prep_kernel(const float* __restrict__ x, const float* __restrict__ awq) {
    const int idx = blockIdx.x * blockDim.x + threadIdx.x;
    const int k  = idx & (KDIM - 1);
    const int mq = idx >> 13;              // 0..3 -> m rows 4mq..4mq+3
    const float a = awq[k];
    float v[4];
    #pragma unroll
    for (int i = 0; i < 4; i++)
        v[i] = x[(size_t)(4 * mq + i) * KDIM + k] / a;
    *reinterpret_cast<float4*>(&g_x2t[(size_t)k * MROWS + 4 * mq]) =
        make_float4(v[0], v[1], v[2], v[3]);
}

// -------- dummy: keep gemv at ncu's captured launch slot (slot 3 of 6) --------
__global__ void dummy_kernel() {}

// ---------------- Kernel 2: mixed int4/int8 GEMV, SCALAR FFMA ----------------
// grid = (16 colblocks, 16 k-segs) = 256 blocks, single wave at occ 2.
// 2 cols/thread; x tile (512 k x 16 m, 32 KB) loaded once per block, broadcast
// LDS.128 reads; weights cp.async double-buffered (coalesced gmem, clean LDS).
// Accumulators: 2 x 16 scalar floats = 32 regs -> ~80 regs total, no spill.
__global__ void __launch_bounds__(TPB, 2) gemv_kernel(
    const int4* __restrict__ w4,   // w_int4 as int4 vectors (k-major rows)
    const float* __restrict__ s4,  // s_int4 [N4][64]
    const int4* __restrict__ w8)   // w_uint8 as int4 vectors
{
    __shared__ float xs[KSPAN][MROWS];               // 32 KB static x tile
    extern __shared__ __align__(16) int4 ws[];       // [2][4][512] dynamic 64 KB

    const int tid = threadIdx.x;
    const int nbc = blockIdx.x;          // colblock
    const int ks  = blockIdx.y;          // k-segment
    const int k0  = ks * KSPAN;
    const int colbase = nbc * COLSPB;
    const bool is4 = (colbase < N4);     // uniform per block (6144/512 = 12)

    const int4* wsrc = is4 ? (w4 + (size_t)colbase * (KDIM / 4) + (k0 / 4))
                           : (w8 + (size_t)(colbase - N4) * (KDIM / 4) + (k0 / 4));

    // ---- stage weight chunk c into buffer st (coalesced 64B runs per col) ----
    auto stage = [&](int st, int c) {
        #pragma unroll
        for (int i = 0; i < 8; i++) {
            const int u   = i * TPB + tid;
            const int col = u >> 2;
            const int iw  = u & 3;
            cpasync16(&ws[st * WS_INT4S + iw * COLSPB + col],
                      wsrc + (size_t)col * (KDIM / 4) + c * 4 + iw);
        }
        cp_commit();
    };

    stage(0, 0);
    stage(1, 1);

    // load x tile once (g_x2t tile is L2-hot: reused by all 16 colblocks)
    {
        const float4* src = reinterpret_cast<const float4*>(g_x2t + (size_t)k0 * MROWS);
        float4* dst = reinterpret_cast<float4*>(&xs[0][0]);
        #pragma unroll
        for (int i = tid; i < KSPAN * MROWS / 4; i += TPB)
            dst[i] = src[i];
    }

    float acc0[MROWS], acc1[MROWS];
    #pragma unroll
    for (int m = 0; m < MROWS; m++) { acc0[m] = 0.0f; acc1[m] = 0.0f; }

    const float CB = is4 ? -8388616.0f    // -(2^23 + 8)
                         : -8388736.0f;   // -(2^23 + 128)

    float s0 = 1.0f, s1 = 1.0f;
    for (int c = 0; c < NCHUNK; c++) {
        // group scale: 128 k = 8 chunks
        if (is4 && (c & 7) == 0) {
            const int gidx = (k0 + c * CHUNKK) >> 7;
            s0 = s4[(size_t)(colbase + tid) * (KDIM / 128) + gidx];
            s1 = s4[(size_t)(colbase + TPB + tid) * (KDIM / 128) + gidx];
        }

        if (c == NCHUNK - 1) cp_wait<0>(); else cp_wait<1>();
        __syncthreads();
        const int b = c & 1;

        #pragma unroll
        for (int iw = 0; iw < 4; iw++) {    // 4 k per iw
            const int4 wA = ws[b * WS_INT4S + iw * COLSPB + tid];
            const int4 wB = ws[b * WS_INT4S + iw * COLSPB + TPB + tid];

            #pragma unroll
            for (int e = 0; e < 4; e++) {
                const int wa = (e == 0) ? wA.x : (e == 1) ? wA.y : (e == 2) ? wA.z : wA.w;
                const int wb = (e == 0) ? wB.x : (e == 1) ? wB.y : (e == 2) ? wB.z : wB.w;
                // exact dequant: (2^23+w) - (2^23+bias), then single-rounded * s
                const float dA = biasf(wa) + CB;
                const float dB = biasf(wb) + CB;
                const float wdA = is4 ? dA * s0 : dA;
                const float wdB = is4 ? dB * s1 : dB;

                const int k = c * CHUNKK + iw * 4 + e;
                const float4 x0 = *reinterpret_cast<const float4*>(&xs[k][0]);
                const float4 x1 = *reinterpret_cast<const float4*>(&xs[k][4]);
                const float4 x2 = *reinterpret_cast<const float4*>(&xs[k][8]);
                const float4 x3 = *reinterpret_cast<const float4*>(&xs[k][12]);

                acc0[0]  = fmaf(x0.x, wdA, acc0[0]);
                acc0[1]  = fmaf(x0.y, wdA, acc0[1]);
                acc0[2]  = fmaf(x0.z, wdA, acc0[2]);
                acc0[3]  = fmaf(x0.w, wdA, acc0[3]);
                acc0[4]  = fmaf(x1.x, wdA, acc0[4]);
                acc0[5]  = fmaf(x1.y, wdA, acc0[5]);
                acc0[6]  = fmaf(x1.z, wdA, acc0[6]);
                acc0[7]  = fmaf(x1.w, wdA, acc0[7]);
                acc0[8]  = fmaf(x2.x, wdA, acc0[8]);
                acc0[9]  = fmaf(x2.y, wdA, acc0[9]);
                acc0[10] = fmaf(x2.z, wdA, acc0[10]);
                acc0[11] = fmaf(x2.w, wdA, acc0[11]);
                acc0[12] = fmaf(x3.x, wdA, acc0[12]);
                acc0[13] = fmaf(x3.y, wdA, acc0[13]);
                acc0[14] = fmaf(x3.z, wdA, acc0[14]);
                acc0[15] = fmaf(x3.w, wdA, acc0[15]);

                acc1[0]  = fmaf(x0.x, wdB, acc1[0]);
                acc1[1]  = fmaf(x0.y, wdB, acc1[1]);
                acc1[2]  = fmaf(x0.z, wdB, acc1[2]);
                acc1[3]  = fmaf(x0.w, wdB, acc1[3]);
                acc1[4]  = fmaf(x1.x, wdB, acc1[4]);
                acc1[5]  = fmaf(x1.y, wdB, acc1[5]);
                acc1[6]  = fmaf(x1.z, wdB, acc1[6]);
                acc1[7]  = fmaf(x1.w, wdB, acc1[7]);
                acc1[8]  = fmaf(x2.x, wdB, acc1[8]);
                acc1[9]  = fmaf(x2.y, wdB, acc1[9]);
                acc1[10] = fmaf(x2.z, wdB, acc1[10]);
                acc1[11] = fmaf(x2.w, wdB, acc1[11]);
                acc1[12] = fmaf(x3.x, wdB, acc1[12]);
                acc1[13] = fmaf(x3.y, wdB, acc1[13]);
                acc1[14] = fmaf(x3.z, wdB, acc1[14]);
                acc1[15] = fmaf(x3.w, wdB, acc1[15]);
            }
        }

        __syncthreads();                    // buffer b fully consumed
        if (c + 2 < NCHUNK) stage(b, c + 2);
    }

    // write partial slab (coalesced per m)
    #pragma unroll
    for (int m = 0; m < MROWS; m++) {
        g_part[ks][m][colbase + tid]       = acc0[m];
        g_part[ks][m][colbase + TPB + tid] = acc1[m];
    }
}

// -------- Kernel 3a: coalesced slab reduction --------
__global__ void sum_kernel() {
    const int idx = blockIdx.x * blockDim.x + threadIdx.x;   // 131072
    const int n = idx & (NTOT - 1);
    const int m = idx >> 13;
    float v = 0.0f;
    #pragma unroll
    for (int ks = 0; ks < KSEGS; ks++)
        v += g_part[ks][m][n];
    g_sum[m][n] = v;
}

// -------- Kernel 3b: permute + s8 scale + bias --------
__global__ void permute_kernel(const float* __restrict__ s8,
                               const float* __restrict__ bias,
                               const int* __restrict__ inv_perm,
                               float* __restrict__ out)
{
    const int j = blockIdx.x * blockDim.x + threadIdx.x;   // 8192
    const int p = inv_perm[j];
    const float s = (p >= N4) ? s8[p - N4] : 1.0f;
    const float b = bias[j];
    #pragma unroll
    for (int m = 0; m < MROWS; m++)
        out[m * NTOT + j] = g_sum[m][p] * s + b;
}

extern "C" void kernel_launch(void* const* d_in, const int* in_sizes, int n_in,
                              void* d_out, int out_size)
{
    const float* x    = (const float*)d_in[0];
    const int*   w4   = (const int*)  d_in[1];
    const float* s4   = (const float*)d_in[2];
    const int*   w8   = (const int*)  d_in[3];
    const float* s8   = (const float*)d_in[4];
    const float* awq  = (const float*)d_in[5];
    const float* bias = (const float*)d_in[6];
    const int*   ip   = (const int*)  d_in[7];
    float* out = (float*)d_out;

    // raise dynamic smem limit (attribute set, not an allocation; idempotent)
    static bool attr_done = false;
    if (!attr_done) {
        cudaFuncSetAttribute(gemv_kernel,
                             cudaFuncAttributeMaxDynamicSharedMemorySize, SMEM_BYTES);
        attr_done = true;
    }

    // 6 launches/call keeps gemv at ncu's captured slot (slot 3).
    prep_kernel<<<128, 256>>>(x, awq);                       // slot 0 (32768 threads)
    dummy_kernel<<<1, 32>>>();                               // slot 1
    dummy_kernel<<<1, 32>>>();                               // slot 2

    dim3 grid(NTOT / COLSPB, KSEGS);                         // (16, 16) = 256 blocks
    gemv_kernel<<<grid, TPB, SMEM_BYTES>>>((const int4*)w4, s4, (const int4*)w8);  // slot 3

    sum_kernel<<<512, 256>>>();                              // slot 4
    permute_kernel<<<NTOT / 256, 256>>>(s8, bias, ip, out);  // slot 5
}

// round 14
// speedup vs baseline: 1.1705x; 1.1705x over previous
#include <cuda_runtime.h>
#include <cstdint>

#define KDIM   8192
#define N4     6144
#define N8     2048
#define NTOT   8192
#define MROWS  16
#define KSEGS  8
#define KSPAN  1024               // K per block
#define CHUNKK 16                 // k per per-warp pipeline chunk
#define NCHUNK 64                 // KSPAN / CHUNKK
#define HALFCH 32                 // chunks per x half-tile
#define COLSPB 256                // columns per block (1 per thread)
#define TPB    256
#define DEPTH  4                  // per-warp ring depth

// dynamic smem: x half-tile 32 KB + per-warp weight rings 8*4*2KB = 64 KB
#define SMEM_BYTES (32768 + 65536)

typedef unsigned long long ull;

// Scratch (device globals; no runtime allocation)
__device__ __align__(16) ull   g_x2p[KDIM / 2][MROWS];        // 512 KB k-pair packed x2
__device__ __align__(16) float g_part[KSEGS][MROWS][NTOT];    // 4 MB partial slabs
__device__ __align__(16) float g_sum[MROWS][NTOT];            // 512 KB

// ---- Blackwell packed fp32 ops (sm_100+; ptxas never auto-emits these) ----
__device__ __forceinline__ ull ffma2(ull a, ull b, ull c) {
    ull d;
    asm("fma.rn.f32x2 %0, %1, %2, %3;" : "=l"(d) : "l"(a), "l"(b), "l"(c));
    return d;
}
__device__ __forceinline__ ull fadd2(ull a, ull b) {
    ull d;
    asm("add.rn.f32x2 %0, %1, %2;" : "=l"(d) : "l"(a), "l"(b));
    return d;
}
__device__ __forceinline__ ull fmul2(ull a, ull b) {
    ull d;
    asm("mul.rn.f32x2 %0, %1, %2;" : "=l"(d) : "l"(a), "l"(b));
    return d;
}
__device__ __forceinline__ ull pack2(float lo, float hi) {
    ull r;
    asm("mov.b64 %0, {%1, %2};" : "=l"(r) : "f"(lo), "f"(hi));
    return r;
}
__device__ __forceinline__ float2 unpack2(ull v) {
    float2 f;
    asm("mov.b64 {%0, %1}, %2;" : "=f"(f.x), "=f"(f.y) : "l"(v));
    return f;
}
// int (0 <= w < 2^22) -> float(2^23 + w), exact, one LOP3
__device__ __forceinline__ float biasf(int w) {
    return __uint_as_float(0x4B000000u | (unsigned)w);
}
// cp.async 16B, global -> shared, L2-only (.cg)
__device__ __forceinline__ void cpasync16(void* smem, const void* gmem) {
    uint32_t s = (uint32_t)__cvta_generic_to_shared(smem);
    asm volatile("cp.async.cg.shared.global [%0], [%1], 16;" :: "r"(s), "l"(gmem) : "memory");
}
__device__ __forceinline__ void cp_commit() {
    asm volatile("cp.async.commit_group;" ::: "memory");
}
template <int N>
__device__ __forceinline__ void cp_wait() {
    asm volatile("cp.async.wait_group %0;" :: "n"(N) : "memory");
}

// -------- Kernel 1: g_x2p[kp][m] = pack(x[m][2kp]/awq[2kp], x[m][2kp+1]/awq[2kp+1]) --------
// 32768 threads, each owns a distinct 16B (kp, m-pair) cell — no aliasing (R11-verified).
__global__ void prep_kernel(const float* __restrict__ x, const float* __restrict__ awq) {
    const int idx = blockIdx.x * blockDim.x + threadIdx.x;   // 32768
    const int kp = idx & 4095;
    const int mq = idx >> 12;          // 0..7 -> m rows 2mq, 2mq+1
    const float2 a = *reinterpret_cast<const float2*>(awq + 2 * kp);
    ull p0, p1;
    {
        const float2 xv = *reinterpret_cast<const float2*>(x + (size_t)(2 * mq) * KDIM + 2 * kp);
        p0 = pack2(xv.x / a.x, xv.y / a.y);
    }
    {
        const float2 xv = *reinterpret_cast<const float2*>(x + (size_t)(2 * mq + 1) * KDIM + 2 * kp);
        p1 = pack2(xv.x / a.x, xv.y / a.y);
    }
    *reinterpret_cast<ulonglong2*>(&g_x2p[kp][2 * mq]) = make_ulonglong2(p0, p1);
}

// -------- dummy: keep gemv at ncu's captured launch slot (slot 3 of 6) --------
__global__ void dummy_kernel() {}

// ---------------- Kernel 2: mixed int4/int8 GEMV, warp-autonomous pipeline ----------------
// grid = (32 colblocks, 8 k-segs) = 256 blocks, single wave at occ 2 (96 KB smem).
// Each warp owns 32 columns + a private DEPTH-4 cp.async ring of 2 KB weight
// chunks, synced ONLY with wait_group + __syncwarp (no block barriers in the
// mainloop — 3 __syncthreads total, for the two x half-tiles).
// 1 col/thread; acc = 16 k-parity-packed f32x2 ulls = 32 regs.
__global__ void __launch_bounds__(TPB, 2) gemv_kernel(
    const int4* __restrict__ w4,   // w_int4 as int4 vectors (k-major rows)
    const float* __restrict__ s4,  // s_int4 [N4][64]
    const int4* __restrict__ w8)   // w_uint8 as int4 vectors
{
    extern __shared__ __align__(16) char dynsmem[];
    ull*  xs    = reinterpret_cast<ull*>(dynsmem);            // [256 kp][16 m]  (32 KB half-tile)
    int4* wring = reinterpret_cast<int4*>(dynsmem + 32768);   // [8 warps][4 st][4 iw][32 col]

    const int tid  = threadIdx.x;
    const int warp = tid >> 5;
    const int lane = tid & 31;
    const int nbc  = blockIdx.x;         // colblock 0..31 (0..23 int4, 24..31 uint8)
    const int ks   = blockIdx.y;         // k-segment 0..7
    const int k0   = ks * KSPAN;
    const int outcol = nbc * COLSPB + warp * 32 + lane;
    const bool is4 = (nbc < 24);
    const int wcolbase = is4 ? (nbc * COLSPB + warp * 32)
                             : (nbc * COLSPB + warp * 32 - N4);
    const int4* wsrc = (is4 ? w4 : w8) + (size_t)wcolbase * (KDIM / 4) + (k0 / 4);
    int4* myring = wring + warp * (DEPTH * 4 * 32);

    // warp-cooperative stage of chunk c (16 k x 32 cols = 2 KB) into ring slot s.
    // gmem: per i, 8 cols x 64B contiguous runs (coalesced). smem: [iw][col].
    auto stage = [&](int s, int c) {
        #pragma unroll
        for (int i = 0; i < 4; i++) {
            const int u    = i * 32 + lane;
            const int colL = u >> 2;
            const int iw   = u & 3;
            cpasync16(&myring[s * 128 + iw * 32 + colL],
                      wsrc + (size_t)colL * (KDIM / 4) + c * 4 + iw);
        }
        cp_commit();
    };
    // block-cooperative x half-tile stage (512 k = 256 kp = 32 KB contiguous)
    auto stage_x = [&](int half) {
        const float4* src = reinterpret_cast<const float4*>(&g_x2p[(k0 + half * 512) / 2][0]);
        float4* dst = reinterpret_cast<float4*>(xs);
        #pragma unroll
        for (int i = tid; i < 2048; i += TPB)
            dst[i] = src[i];
    };

    stage(0, 0); stage(1, 1); stage(2, 2); stage(3, 3);
    stage_x(0);
    __syncthreads();

    ull acc[MROWS];
    #pragma unroll
    for (int m = 0; m < MROWS; m++) acc[m] = 0ull;

    const float CBs = is4 ? -8388616.0f : -8388736.0f;   // -(2^23 + 8) / -(2^23 + 128)
    const ull CBp = pack2(CBs, CBs);
    ull spp = pack2(1.0f, 1.0f);                          // stays 1 for uint8 path

    for (int c = 0; c < NCHUNK; c++) {
        if (c == HALFCH) {                 // swap x half-tile (2 of the 3 total barriers)
            __syncthreads();
            stage_x(1);
            __syncthreads();
        }
        if (is4 && (c & 7) == 0) {         // 128-k scale group = 8 chunks
            const float s = s4[(size_t)outcol * (KDIM / 128) + (k0 >> 7) + (c >> 3)];
            spp = pack2(s, s);
        }

        cp_wait<DEPTH - 1>();              // oldest ring slot landed (per-thread)
        __syncwarp();                      // make peers' staged bytes visible

        const int s = c & (DEPTH - 1);
        int4 w[4];
        #pragma unroll
        for (int iw = 0; iw < 4; iw++)
            w[iw] = myring[s * 128 + iw * 32 + lane];   // 512B contiguous per warp
        __syncwarp();                      // all reads done before slot reuse
        if (c + DEPTH < NCHUNK) stage(s, c + DEPTH);

        #pragma unroll
        for (int iw = 0; iw < 4; iw++) {   // 4 k per iw
            // exact dequant, k-pair packed: ((2^23+w)-(2^23+b)) * s
            ull w01 = fmul2(fadd2(pack2(biasf(w[iw].x), biasf(w[iw].y)), CBp), spp);
            ull w23 = fmul2(fadd2(pack2(biasf(w[iw].z), biasf(w[iw].w)), CBp), spp);

            const int kp0 = (c & (HALFCH - 1)) * 8 + iw * 2;
            const ull* x0 = &xs[(size_t)kp0 * MROWS];
            const ull* x1 = x0 + MROWS;
            #pragma unroll
            for (int q = 0; q < 8; q++) {  // 16 m as 8 broadcast ull2 pairs
                const ulonglong2 xa = *reinterpret_cast<const ulonglong2*>(&x0[2 * q]);
                const ulonglong2 xb = *reinterpret_cast<const ulonglong2*>(&x1[2 * q]);
                acc[2 * q]     = ffma2(xa.x, w01, acc[2 * q]);
                acc[2 * q + 1] = ffma2(xa.y, w01, acc[2 * q + 1]);
                acc[2 * q]     = ffma2(xb.x, w23, acc[2 * q]);
                acc[2 * q + 1] = ffma2(xb.y, w23, acc[2 * q + 1]);
            }
        }
    }

    // write partial slab (coalesced per m across the warp)
    #pragma unroll
    for (int m = 0; m < MROWS; m++) {
        const float2 t = unpack2(acc[m]);
        g_part[ks][m][outcol] = t.x + t.y;
    }
}

// -------- Kernel 3a: coalesced slab reduction --------
__global__ void sum_kernel() {
    const int idx = blockIdx.x * blockDim.x + threadIdx.x;   // 131072
    const int n = idx & (NTOT - 1);
    const int m = idx >> 13;
    float v = 0.0f;
    #pragma unroll
    for (int ks = 0; ks < KSEGS; ks++)
        v += g_part[ks][m][n];
    g_sum[m][n] = v;
}

// -------- Kernel 3b: permute + s8 scale + bias --------
__global__ void permute_kernel(const float* __restrict__ s8,
                               const float* __restrict__ bias,
                               const int* __restrict__ inv_perm,
                               float* __restrict__ out)
{
    const int j = blockIdx.x * blockDim.x + threadIdx.x;   // 8192
    const int p = inv_perm[j];
    const float s = (p >= N4) ? s8[p - N4] : 1.0f;
    const float b = bias[j];
    #pragma unroll
    for (int m = 0; m < MROWS; m++)
        out[m * NTOT + j] = g_sum[m][p] * s + b;
}

extern "C" void kernel_launch(void* const* d_in, const int* in_sizes, int n_in,
                              void* d_out, int out_size)
{
    const float* x    = (const float*)d_in[0];
    const int*   w4   = (const int*)  d_in[1];
    const float* s4   = (const float*)d_in[2];
    const int*   w8   = (const int*)  d_in[3];
    const float* s8   = (const float*)d_in[4];
    const float* awq  = (const float*)d_in[5];
    const float* bias = (const float*)d_in[6];
    const int*   ip   = (const int*)  d_in[7];
    float* out = (float*)d_out;

    // raise dynamic smem limit (attribute set, not an allocation; idempotent)
    static bool attr_done = false;
    if (!attr_done) {
        cudaFuncSetAttribute(gemv_kernel,
                             cudaFuncAttributeMaxDynamicSharedMemorySize, SMEM_BYTES);
        attr_done = true;
    }

    // 6 launches/call keeps gemv at ncu's captured slot (slot 3).
    prep_kernel<<<128, 256>>>(x, awq);                       // slot 0 (32768 threads)
    dummy_kernel<<<1, 32>>>();                               // slot 1
    dummy_kernel<<<1, 32>>>();                               // slot 2

    dim3 grid(NTOT / COLSPB, KSEGS);                         // (32, 8) = 256 blocks
    gemv_kernel<<<grid, TPB, SMEM_BYTES>>>((const int4*)w4, s4, (const int4*)w8);  // slot 3

    sum_kernel<<<512, 256>>>();                              // slot 4
    permute_kernel<<<NTOT / 256, 256>>>(s8, bias, ip, out);  // slot 5
}